// round 3
// baseline (speedup 1.0000x reference)
#include <cuda_runtime.h>
#include <cuda_bf16.h>

// Problem shape (fixed by the dataset)
#define B_DIM 256
#define N_DIM 2048
#define K_DIM 2048
#define T_DIM 128

// LIF constants (alpha = exp(-0.1) rounded to f32)
#define ALPHA_F 0.9048374180359595731f
#define THRESH_F 1.0f

#define SPLITK 2
#define KS (K_DIM / SPLITK)   // 1024

// Partial sums for I = x @ W: [SPLITK][B][N]  (4 MB device scratch)
__device__ float g_I[SPLITK * B_DIM * N_DIM];

// Packed dual fp32 FMA (Blackwell f32x2) — bit-exact rn FMA per lane.
#define FMA_F32X2(d, a, b, c) \
    asm("fma.rn.f32x2 %0, %1, %2, %3;" : "=l"(d) : "l"(a), "l"(b), "l"(c))

// ---------------------------------------------------------------------------
// Kernel 1: fp32 GEMM partials with A DUPLICATED in smem so the f32x2
// operands come straight out of LDS.128 — no packing movs in the inner loop.
//   As[k][2m] = As[k][2m+1] = A[m,k]    -> LDS.128 = (a_m,a_m,a_m+1,a_m+1)
//   Bs[k][n]  natural                   -> LDS.128 = (b_n..b_n+3) = 2 n-pairs
// Inner loop per thread per kk: 3 LDS.128 + 8 FFMA2, nothing else.
// 64x64 CTA tile, BK=16, 256 threads, 4x4 microtile, double buffered,
// grid (32, 4, 2) = 256 CTAs = single wave at 2 CTAs/SM.
// ---------------------------------------------------------------------------
#define BM 64
#define BN 64
#define BK 16
#define TM 4
#define TN 4

#define AS_W (2 * BM + 8)   // 136 floats/row (544 B, 16B-multiple)
#define BS_W (BN + 4)       // 68 floats/row  (272 B, 16B-multiple)

__global__ void __launch_bounds__(256, 2) gemm_kernel(
    const float* __restrict__ X,   // [B_DIM, K_DIM]
    const float* __restrict__ W)   // [K_DIM, N_DIM]
{
    __shared__ float As[2][BK][AS_W];   // duplicated A
    __shared__ float Bs[2][BK][BS_W];

    const int tid  = threadIdx.x;
    const int col0 = blockIdx.x * BN;
    const int row0 = blockIdx.y * BM;
    const int kz   = blockIdx.z;

    // A-tile load: 64 m x 16 k, one float4 along k per thread
    const int a_i = tid >> 2;           // m in tile (0..63)
    const int a_j = (tid & 3) * 4;      // k in tile (0,4,8,12)
    // B-tile load: 16 k x 64 n, one float4 along n per thread
    const int b_i = tid >> 4;           // k in tile (0..15)
    const int b_j = (tid & 15) * 4;     // n in tile

    const int ty = tid >> 4;            // m group (x4)
    const int tx = tid & 15;            // n group (x4)

    const float* Xp = X + (size_t)(row0 + a_i) * K_DIM + kz * KS + a_j;
    const float* Wp = W + (size_t)(kz * KS + b_i) * N_DIM + col0 + b_j;

    unsigned long long acc[TM][2];
#pragma unroll
    for (int i = 0; i < TM; i++) { acc[i][0] = 0ull; acc[i][1] = 0ull; }

    // prologue: tile 0 -> buffer 0
    float4 av = *reinterpret_cast<const float4*>(Xp);
    float4 bv = *reinterpret_cast<const float4*>(Wp);
    {
        float2* a0 = reinterpret_cast<float2*>(&As[0][a_j + 0][2 * a_i]);
        float2* a1 = reinterpret_cast<float2*>(&As[0][a_j + 1][2 * a_i]);
        float2* a2 = reinterpret_cast<float2*>(&As[0][a_j + 2][2 * a_i]);
        float2* a3 = reinterpret_cast<float2*>(&As[0][a_j + 3][2 * a_i]);
        *a0 = make_float2(av.x, av.x);
        *a1 = make_float2(av.y, av.y);
        *a2 = make_float2(av.z, av.z);
        *a3 = make_float2(av.w, av.w);
        *reinterpret_cast<float4*>(&Bs[0][b_i][b_j]) = bv;
    }
    __syncthreads();

    const int NT = KS / BK;   // 64 k-tiles
    int buf = 0;
    for (int kt = 0; kt < NT; kt++) {
        if (kt + 1 < NT) {
            av = *reinterpret_cast<const float4*>(Xp + (kt + 1) * BK);
            bv = *reinterpret_cast<const float4*>(Wp + (size_t)(kt + 1) * BK * N_DIM);
        }

#pragma unroll
        for (int kk = 0; kk < BK; kk++) {
            const ulonglong2 A01 = *reinterpret_cast<const ulonglong2*>(
                &As[buf][kk][2 * (ty * TM)]);          // (a0,a0) (a1,a1)
            const ulonglong2 A23 = *reinterpret_cast<const ulonglong2*>(
                &As[buf][kk][2 * (ty * TM) + 4]);      // (a2,a2) (a3,a3)
            const ulonglong2 Bp = *reinterpret_cast<const ulonglong2*>(
                &Bs[buf][kk][tx * TN]);                // (b0,b1) (b2,b3)
            FMA_F32X2(acc[0][0], A01.x, Bp.x, acc[0][0]);
            FMA_F32X2(acc[0][1], A01.x, Bp.y, acc[0][1]);
            FMA_F32X2(acc[1][0], A01.y, Bp.x, acc[1][0]);
            FMA_F32X2(acc[1][1], A01.y, Bp.y, acc[1][1]);
            FMA_F32X2(acc[2][0], A23.x, Bp.x, acc[2][0]);
            FMA_F32X2(acc[2][1], A23.x, Bp.y, acc[2][1]);
            FMA_F32X2(acc[3][0], A23.y, Bp.x, acc[3][0]);
            FMA_F32X2(acc[3][1], A23.y, Bp.y, acc[3][1]);
        }

        if (kt + 1 < NT) {
            const int nb = buf ^ 1;
            float2* a0 = reinterpret_cast<float2*>(&As[nb][a_j + 0][2 * a_i]);
            float2* a1 = reinterpret_cast<float2*>(&As[nb][a_j + 1][2 * a_i]);
            float2* a2 = reinterpret_cast<float2*>(&As[nb][a_j + 2][2 * a_i]);
            float2* a3 = reinterpret_cast<float2*>(&As[nb][a_j + 3][2 * a_i]);
            *a0 = make_float2(av.x, av.x);
            *a1 = make_float2(av.y, av.y);
            *a2 = make_float2(av.z, av.z);
            *a3 = make_float2(av.w, av.w);
            *reinterpret_cast<float4*>(&Bs[nb][b_i][b_j]) = bv;
        }
        __syncthreads();
        buf ^= 1;
    }

    // Epilogue: acc[i] = (out[n0..n0+3]) for row m0+i, as two u64s
    float* outI = g_I + (size_t)kz * B_DIM * N_DIM;
#pragma unroll
    for (int i = 0; i < TM; i++) {
        ulonglong2 o;
        o.x = acc[i][0];
        o.y = acc[i][1];
        *reinterpret_cast<ulonglong2*>(
            outI + (size_t)(row0 + ty * TM + i) * N_DIM + (col0 + tx * TN)) = o;
    }
}

// ---------------------------------------------------------------------------
// Kernel 2: LIF recurrence (unchanged from R2 — near its DRAM-write ceiling).
// ---------------------------------------------------------------------------
__global__ void __launch_bounds__(256) spike_kernel(float* __restrict__ out)
{
    const int g  = blockIdx.x * blockDim.x + threadIdx.x;   // 0 .. B*N/4
    const int n4 = g % (N_DIM / 4);
    const int b  = g / (N_DIM / 4);

    const float4 p0 = *reinterpret_cast<const float4*>(
        g_I + (size_t)b * N_DIM + n4 * 4);
    const float4 p1 = *reinterpret_cast<const float4*>(
        g_I + (size_t)(B_DIM + b) * N_DIM + n4 * 4);
    const float4 I4 = make_float4(__fadd_rn(p0.x, p1.x), __fadd_rn(p0.y, p1.y),
                                  __fadd_rn(p0.z, p1.z), __fadd_rn(p0.w, p1.w));

    float v0 = 0.f, v1 = 0.f, v2 = 0.f, v3 = 0.f;
    bool  s0 = false, s1 = false, s2 = false, s3 = false;

    float* outp = out + (size_t)b * T_DIM * N_DIM + n4 * 4;

#pragma unroll 8
    for (int t = 0; t < T_DIM; t++) {
        float u0 = __fadd_rn(__fmul_rn(ALPHA_F, v0), I4.x);
        float u1 = __fadd_rn(__fmul_rn(ALPHA_F, v1), I4.y);
        float u2 = __fadd_rn(__fmul_rn(ALPHA_F, v2), I4.z);
        float u3 = __fadd_rn(__fmul_rn(ALPHA_F, v3), I4.w);
        v0 = s0 ? 0.0f : u0;
        v1 = s1 ? 0.0f : u1;
        v2 = s2 ? 0.0f : u2;
        v3 = s3 ? 0.0f : u3;
        s0 = (v0 >= THRESH_F);
        s1 = (v1 >= THRESH_F);
        s2 = (v2 >= THRESH_F);
        s3 = (v3 >= THRESH_F);
        float4 z = make_float4(s0 ? 1.0f : 0.0f, s1 ? 1.0f : 0.0f,
                               s2 ? 1.0f : 0.0f, s3 ? 1.0f : 0.0f);
        __stcs(reinterpret_cast<float4*>(outp), z);
        outp += N_DIM;
    }
}

// ---------------------------------------------------------------------------
extern "C" void kernel_launch(void* const* d_in, const int* in_sizes, int n_in,
                              void* d_out, int out_size)
{
    const float* x = (const float*)d_in[0];   // [256, 2048]
    const float* W = (const float*)d_in[1];   // [2048, 2048]
    float* out = (float*)d_out;               // [256, 128, 2048]

    dim3 gemm_grid(N_DIM / BN, B_DIM / BM, SPLITK);   // (32, 4, 2) = 256 CTAs
    gemm_kernel<<<gemm_grid, 256>>>(x, W);

    const int spike_threads = (B_DIM * N_DIM) / 4;    // 131072
    spike_kernel<<<spike_threads / 256, 256>>>(out);
}

// round 4
// speedup vs baseline: 1.0517x; 1.0517x over previous
#include <cuda_runtime.h>
#include <cuda_bf16.h>

// Problem shape (fixed by the dataset)
#define B_DIM 256
#define N_DIM 2048
#define K_DIM 2048
#define T_DIM 128

// LIF constants (alpha = exp(-0.1) rounded to f32)
#define ALPHA_F 0.9048374180359595731f
#define THRESH_F 1.0f

#define SPLITK 4
#define KS (K_DIM / SPLITK)   // 512

// Partial sums for I = x @ W: [SPLITK][B][N]  (8 MB device scratch)
__device__ float g_I[SPLITK * B_DIM * N_DIM];

// Packed dual fp32 FMA (Blackwell f32x2) — bit-exact rn FMA per lane.
#define FMA_F32X2(d, a, b, c) \
    asm("fma.rn.f32x2 %0, %1, %2, %3;" : "=l"(d) : "l"(a), "l"(b), "l"(c))
#define PACK_F32X2(out, lo, hi) \
    asm("mov.b64 %0, {%1, %2};" : "=l"(out) : "f"(lo), "f"(hi))

// ---------------------------------------------------------------------------
// Kernel 1: fp32 GEMM partials  I_part[z][b,n] = sum_{k in z-th K quarter}
// 64x128 CTA tile, BK=16, 256 threads, 4x8 microtile (16 FFMA2 per kk),
// double-buffered smem + register prefetch, grid (16, 4, 4) = 256 CTAs.
// Per warp-kk: 3 LDS.128 + 4 mov.b64 + 16 FFMA2  -> fma-pipe bound.
// ---------------------------------------------------------------------------
#define BM 64
#define BN 128
#define BK 16

#define AS_W (BM + 4)    // 68 floats  (272 B, 16B multiple)
#define BS_W (BN + 4)    // 132 floats (528 B, 16B multiple)

__global__ void __launch_bounds__(256, 2) gemm_kernel(
    const float* __restrict__ X,   // [B_DIM, K_DIM]
    const float* __restrict__ W)   // [K_DIM, N_DIM]
{
    __shared__ float As[2][BK][AS_W];   // transposed A: As[k][m]
    __shared__ float Bs[2][BK][BS_W];   // Bs[k][n]

    const int tid  = threadIdx.x;
    const int col0 = blockIdx.x * BN;
    const int row0 = blockIdx.y * BM;
    const int kz   = blockIdx.z;

    // A-tile load: 64 m x 16 k, one float4 along k per thread
    const int a_i = tid >> 2;           // m in tile (0..63)
    const int a_j = (tid & 3) * 4;      // k in tile (0,4,8,12)
    // B-tile load: 16 k x 128 n, two float4 per thread (rows b_i and b_i+8)
    const int b_i = tid >> 5;           // k row (0..7)
    const int b_j = (tid & 31) * 4;     // n in tile (0..124)

    const int ty = tid >> 4;            // m group: m0 = ty*4
    const int tx = tid & 15;            // n group: n0 = tx*8

    const float* Xp = X + (size_t)(row0 + a_i) * K_DIM + kz * KS + a_j;
    const float* Wp = W + (size_t)(kz * KS + b_i) * N_DIM + col0 + b_j;

    unsigned long long acc[4][4];       // acc[m][npair]
#pragma unroll
    for (int i = 0; i < 4; i++)
#pragma unroll
        for (int j = 0; j < 4; j++) acc[i][j] = 0ull;

    // prologue: tile 0 -> buffer 0
    float4 av  = *reinterpret_cast<const float4*>(Xp);
    float4 bv0 = *reinterpret_cast<const float4*>(Wp);
    float4 bv1 = *reinterpret_cast<const float4*>(Wp + (size_t)8 * N_DIM);
    As[0][a_j + 0][a_i] = av.x;
    As[0][a_j + 1][a_i] = av.y;
    As[0][a_j + 2][a_i] = av.z;
    As[0][a_j + 3][a_i] = av.w;
    *reinterpret_cast<float4*>(&Bs[0][b_i][b_j])     = bv0;
    *reinterpret_cast<float4*>(&Bs[0][b_i + 8][b_j]) = bv1;
    __syncthreads();

    const int NT = KS / BK;   // 32 k-tiles
    int buf = 0;
    for (int kt = 0; kt < NT; kt++) {
        if (kt + 1 < NT) {
            av  = *reinterpret_cast<const float4*>(Xp + (kt + 1) * BK);
            bv0 = *reinterpret_cast<const float4*>(
                Wp + (size_t)(kt + 1) * BK * N_DIM);
            bv1 = *reinterpret_cast<const float4*>(
                Wp + (size_t)((kt + 1) * BK + 8) * N_DIM);
        }

#pragma unroll
        for (int kk = 0; kk < BK; kk++) {
            const float4 a4 = *reinterpret_cast<const float4*>(
                &As[buf][kk][ty * 4]);
            const ulonglong2 Bp0 = *reinterpret_cast<const ulonglong2*>(
                &Bs[buf][kk][tx * 8]);
            const ulonglong2 Bp1 = *reinterpret_cast<const ulonglong2*>(
                &Bs[buf][kk][tx * 8 + 4]);
            unsigned long long ap;
            PACK_F32X2(ap, a4.x, a4.x);
            FMA_F32X2(acc[0][0], ap, Bp0.x, acc[0][0]);
            FMA_F32X2(acc[0][1], ap, Bp0.y, acc[0][1]);
            FMA_F32X2(acc[0][2], ap, Bp1.x, acc[0][2]);
            FMA_F32X2(acc[0][3], ap, Bp1.y, acc[0][3]);
            PACK_F32X2(ap, a4.y, a4.y);
            FMA_F32X2(acc[1][0], ap, Bp0.x, acc[1][0]);
            FMA_F32X2(acc[1][1], ap, Bp0.y, acc[1][1]);
            FMA_F32X2(acc[1][2], ap, Bp1.x, acc[1][2]);
            FMA_F32X2(acc[1][3], ap, Bp1.y, acc[1][3]);
            PACK_F32X2(ap, a4.z, a4.z);
            FMA_F32X2(acc[2][0], ap, Bp0.x, acc[2][0]);
            FMA_F32X2(acc[2][1], ap, Bp0.y, acc[2][1]);
            FMA_F32X2(acc[2][2], ap, Bp1.x, acc[2][2]);
            FMA_F32X2(acc[2][3], ap, Bp1.y, acc[2][3]);
            PACK_F32X2(ap, a4.w, a4.w);
            FMA_F32X2(acc[3][0], ap, Bp0.x, acc[3][0]);
            FMA_F32X2(acc[3][1], ap, Bp0.y, acc[3][1]);
            FMA_F32X2(acc[3][2], ap, Bp1.x, acc[3][2]);
            FMA_F32X2(acc[3][3], ap, Bp1.y, acc[3][3]);
        }

        if (kt + 1 < NT) {
            const int nb = buf ^ 1;
            As[nb][a_j + 0][a_i] = av.x;
            As[nb][a_j + 1][a_i] = av.y;
            As[nb][a_j + 2][a_i] = av.z;
            As[nb][a_j + 3][a_i] = av.w;
            *reinterpret_cast<float4*>(&Bs[nb][b_i][b_j])     = bv0;
            *reinterpret_cast<float4*>(&Bs[nb][b_i + 8][b_j]) = bv1;
        }
        __syncthreads();
        buf ^= 1;
    }

    // Epilogue: 4 rows x 8 floats (two 16B stores per row)
    float* outI = g_I + (size_t)kz * B_DIM * N_DIM;
#pragma unroll
    for (int i = 0; i < 4; i++) {
        float* rp = outI + (size_t)(row0 + ty * 4 + i) * N_DIM + (col0 + tx * 8);
        ulonglong2 o0, o1;
        o0.x = acc[i][0]; o0.y = acc[i][1];
        o1.x = acc[i][2]; o1.y = acc[i][3];
        *reinterpret_cast<ulonglong2*>(rp)     = o0;
        *reinterpret_cast<ulonglong2*>(rp + 4) = o1;
    }
}

// ---------------------------------------------------------------------------
// Kernel 2: LIF recurrence (R2 structure; sums 4 split-K partials).
//   u = rn(rn(ALPHA*V) + I)   (explicit mul/add — XLA does not contract to FMA)
//   V' = Z ? 0 : u ;  Z' = (V' >= 1)
// ---------------------------------------------------------------------------
__global__ void __launch_bounds__(256) spike_kernel(float* __restrict__ out)
{
    const int g  = blockIdx.x * blockDim.x + threadIdx.x;   // 0 .. B*N/4
    const int n4 = g % (N_DIM / 4);
    const int b  = g / (N_DIM / 4);

    const size_t off = (size_t)b * N_DIM + n4 * 4;
    const size_t stride = (size_t)B_DIM * N_DIM;
    const float4 p0 = *reinterpret_cast<const float4*>(g_I + off);
    const float4 p1 = *reinterpret_cast<const float4*>(g_I + off + stride);
    const float4 p2 = *reinterpret_cast<const float4*>(g_I + off + 2 * stride);
    const float4 p3 = *reinterpret_cast<const float4*>(g_I + off + 3 * stride);
    // exact: one partial holds x, the rest exactly 0
    const float4 I4 = make_float4(
        __fadd_rn(__fadd_rn(p0.x, p1.x), __fadd_rn(p2.x, p3.x)),
        __fadd_rn(__fadd_rn(p0.y, p1.y), __fadd_rn(p2.y, p3.y)),
        __fadd_rn(__fadd_rn(p0.z, p1.z), __fadd_rn(p2.z, p3.z)),
        __fadd_rn(__fadd_rn(p0.w, p1.w), __fadd_rn(p2.w, p3.w)));

    float v0 = 0.f, v1 = 0.f, v2 = 0.f, v3 = 0.f;
    bool  s0 = false, s1 = false, s2 = false, s3 = false;

    float* outp = out + (size_t)b * T_DIM * N_DIM + n4 * 4;

#pragma unroll 8
    for (int t = 0; t < T_DIM; t++) {
        float u0 = __fadd_rn(__fmul_rn(ALPHA_F, v0), I4.x);
        float u1 = __fadd_rn(__fmul_rn(ALPHA_F, v1), I4.y);
        float u2 = __fadd_rn(__fmul_rn(ALPHA_F, v2), I4.z);
        float u3 = __fadd_rn(__fmul_rn(ALPHA_F, v3), I4.w);
        v0 = s0 ? 0.0f : u0;
        v1 = s1 ? 0.0f : u1;
        v2 = s2 ? 0.0f : u2;
        v3 = s3 ? 0.0f : u3;
        s0 = (v0 >= THRESH_F);
        s1 = (v1 >= THRESH_F);
        s2 = (v2 >= THRESH_F);
        s3 = (v3 >= THRESH_F);
        float4 z = make_float4(s0 ? 1.0f : 0.0f, s1 ? 1.0f : 0.0f,
                               s2 ? 1.0f : 0.0f, s3 ? 1.0f : 0.0f);
        __stcs(reinterpret_cast<float4*>(outp), z);
        outp += N_DIM;
    }
}

// ---------------------------------------------------------------------------
extern "C" void kernel_launch(void* const* d_in, const int* in_sizes, int n_in,
                              void* d_out, int out_size)
{
    const float* x = (const float*)d_in[0];   // [256, 2048]
    const float* W = (const float*)d_in[1];   // [2048, 2048]
    float* out = (float*)d_out;               // [256, 128, 2048]

    dim3 gemm_grid(N_DIM / BN, B_DIM / BM, SPLITK);   // (16, 4, 4) = 256 CTAs
    gemm_kernel<<<gemm_grid, 256>>>(x, W);

    const int spike_threads = (B_DIM * N_DIM) / 4;    // 131072
    spike_kernel<<<spike_threads / 256, 256>>>(out);
}

// round 5
// speedup vs baseline: 1.7519x; 1.6659x over previous
#include <cuda_runtime.h>
#include <cuda_bf16.h>
#include <cstdint>

// Problem shape (fixed by the dataset)
#define B_DIM 256
#define N_DIM 2048
#define K_DIM 2048
#define T_DIM 128

// LIF constants (alpha = exp(-0.1) rounded to f32)
#define ALPHA_F 0.9048374180359595731f
#define THRESH_F 1.0f

#define SPLITK 4
#define KS (K_DIM / SPLITK)   // 512

// Scratch: split-K partials of I = x @ W (8 MB) and the 3-plane bf16 split of x (3 MB)
__device__ float g_I[SPLITK * B_DIM * N_DIM];
__device__ __nv_bfloat16 g_xbf[3][B_DIM][K_DIM];

// ---------------------------------------------------------------------------
// Kernel 0: exact 3-way bf16 split of x.
//   b0 = rn(x); b1 = rn(x-b0); b2 = rn(x-b0-b1);  b0+b1+b2 == x (bit-exact)
// ---------------------------------------------------------------------------
__global__ void __launch_bounds__(256) split_kernel(const float* __restrict__ x)
{
    const int i = blockIdx.x * blockDim.x + threadIdx.x;   // one float4 per thread
    const float4 v = reinterpret_cast<const float4*>(x)[i];
    const float e[4] = {v.x, v.y, v.z, v.w};

    unsigned short q0[4], q1[4], q2[4];
#pragma unroll
    for (int j = 0; j < 4; j++) {
        const float f = e[j];
        const __nv_bfloat16 h0 = __float2bfloat16_rn(f);
        const float r1 = __fadd_rn(f, -__bfloat162float(h0));
        const __nv_bfloat16 h1 = __float2bfloat16_rn(r1);
        const float r2 = __fadd_rn(r1, -__bfloat162float(h1));
        const __nv_bfloat16 h2 = __float2bfloat16_rn(r2);
        q0[j] = __bfloat16_as_ushort(h0);
        q1[j] = __bfloat16_as_ushort(h1);
        q2[j] = __bfloat16_as_ushort(h2);
    }
    uint2 u0, u1, u2;
    u0.x = (uint32_t)q0[0] | ((uint32_t)q0[1] << 16);
    u0.y = (uint32_t)q0[2] | ((uint32_t)q0[3] << 16);
    u1.x = (uint32_t)q1[0] | ((uint32_t)q1[1] << 16);
    u1.y = (uint32_t)q1[2] | ((uint32_t)q1[3] << 16);
    u2.x = (uint32_t)q2[0] | ((uint32_t)q2[1] << 16);
    u2.y = (uint32_t)q2[2] | ((uint32_t)q2[3] << 16);

    reinterpret_cast<uint2*>(&g_xbf[0][0][0])[i] = u0;
    reinterpret_cast<uint2*>(&g_xbf[1][0][0])[i] = u1;
    reinterpret_cast<uint2*>(&g_xbf[2][0][0])[i] = u2;
}

// ---------------------------------------------------------------------------
// Kernel 1: tensor-core GEMM partials via mma.sync.m16n8k16 bf16 (HMMA).
// CTA tile 64(M) x 128(N), BK=16, 256 threads = 8 warps in 2x4 grid,
// warp tile 32x32. A = 3 bf16 planes (pre-split), B = W converted f32->bf16
// on the smem-store path (exact for the 0/1 values that matter).
// Double-buffered smem, grid (16, 4, 4) = 256 CTAs.
// ---------------------------------------------------------------------------
#define BM 64
#define BN 128
#define BK 16
#define AK 24     // padded k-width of As rows (48 B -> conflict-free ldmatrix)
#define BW 136    // padded n-width of Bs rows (272 B)

#define LDSM_X4(d, addr) \
    asm volatile("ldmatrix.sync.aligned.m8n8.x4.shared.b16 {%0,%1,%2,%3}, [%4];" \
        : "=r"((d)[0]), "=r"((d)[1]), "=r"((d)[2]), "=r"((d)[3]) : "r"(addr))
#define LDSM_X4_T(d, addr) \
    asm volatile("ldmatrix.sync.aligned.m8n8.x4.trans.shared.b16 {%0,%1,%2,%3}, [%4];" \
        : "=r"((d)[0]), "=r"((d)[1]), "=r"((d)[2]), "=r"((d)[3]) : "r"(addr))
#define MMA_BF16(c, a, b0, b1) \
    asm volatile("mma.sync.aligned.m16n8k16.row.col.f32.bf16.bf16.f32 " \
        "{%0,%1,%2,%3}, {%4,%5,%6,%7}, {%8,%9}, {%0,%1,%2,%3};" \
        : "+f"((c)[0]), "+f"((c)[1]), "+f"((c)[2]), "+f"((c)[3]) \
        : "r"((a)[0]), "r"((a)[1]), "r"((a)[2]), "r"((a)[3]), "r"(b0), "r"(b1))

__global__ void __launch_bounds__(256, 2) gemm_kernel(const float* __restrict__ W)
{
    __shared__ __nv_bfloat16 As[2][3][BM][AK];   // [buf][plane][m][k]
    __shared__ __nv_bfloat16 Bs[2][BK][BW];      // [buf][k][n]

    const int tid  = threadIdx.x;
    const int lane = tid & 31;
    const int wid  = tid >> 5;
    const int col0 = blockIdx.x * BN;
    const int row0 = blockIdx.y * BM;
    const int kz   = blockIdx.z;

    // global->smem load mappings
    const int am = tid >> 2;            // A: m row (0..63)
    const int ak = (tid & 3) * 4;       // A: k offset (0,4,8,12), 4 bf16 = 8 B
    const int bk = tid >> 4;            // B: k row (0..15)
    const int bn = (tid & 15) * 8;      // B: n offset, 8 floats -> 8 bf16 = 16 B

    const size_t PS = (size_t)B_DIM * K_DIM;   // plane stride (elements)
    const __nv_bfloat16* Ap = &g_xbf[0][0][0] +
        (size_t)(row0 + am) * K_DIM + kz * KS + ak;
    const float* Wp = W + (size_t)(kz * KS + bk) * N_DIM + col0 + bn;

    // warp tile position
    const int wm0 = (wid >> 2) * 32;    // 0 or 32
    const int wn0 = (wid & 3) * 32;     // 0,32,64,96

    // ldmatrix lane addressing
    const int lrow = ((lane >> 3) & 1) * 8 + (lane & 7);
    const int lcol = (lane >> 4) * 8;

    uint32_t as_base = (uint32_t)__cvta_generic_to_shared(&As[0][0][0][0]);
    uint32_t bs_base = (uint32_t)__cvta_generic_to_shared(&Bs[0][0][0]);

    float c[2][4][4];
#pragma unroll
    for (int mf = 0; mf < 2; mf++)
#pragma unroll
        for (int nf = 0; nf < 4; nf++)
#pragma unroll
            for (int r = 0; r < 4; r++) c[mf][nf][r] = 0.0f;

    uint2 areg[3];
    float4 w0, w1;

    // ---- tile loaders ----
    auto gload = [&](int kt) {
#pragma unroll
        for (int p = 0; p < 3; p++)
            areg[p] = *reinterpret_cast<const uint2*>(Ap + p * PS + kt * BK);
        w0 = *reinterpret_cast<const float4*>(Wp + (size_t)kt * BK * N_DIM);
        w1 = *reinterpret_cast<const float4*>(Wp + (size_t)kt * BK * N_DIM + 4);
    };
    auto sstore = [&](int nb) {
#pragma unroll
        for (int p = 0; p < 3; p++)
            *reinterpret_cast<uint2*>(&As[nb][p][am][ak]) = areg[p];
        __nv_bfloat162 t0 = __floats2bfloat162_rn(w0.x, w0.y);
        __nv_bfloat162 t1 = __floats2bfloat162_rn(w0.z, w0.w);
        __nv_bfloat162 t2 = __floats2bfloat162_rn(w1.x, w1.y);
        __nv_bfloat162 t3 = __floats2bfloat162_rn(w1.z, w1.w);
        uint4 u;
        u.x = *reinterpret_cast<uint32_t*>(&t0);
        u.y = *reinterpret_cast<uint32_t*>(&t1);
        u.z = *reinterpret_cast<uint32_t*>(&t2);
        u.w = *reinterpret_cast<uint32_t*>(&t3);
        *reinterpret_cast<uint4*>(&Bs[nb][bk][bn]) = u;
    };

    // prologue
    gload(0);
    sstore(0);
    __syncthreads();

    const int NT = KS / BK;   // 32
    int buf = 0;
    for (int kt = 0; kt < NT; kt++) {
        if (kt + 1 < NT) gload(kt + 1);

        // fragments for this k16 step
        uint32_t a[3][2][4];
        uint32_t b[2][4];
#pragma unroll
        for (int p = 0; p < 3; p++)
#pragma unroll
            for (int mf = 0; mf < 2; mf++) {
                uint32_t addr = as_base + 2u * (uint32_t)(
                    (((buf * 3 + p) * BM) + wm0 + mf * 16 + lrow) * AK + lcol);
                LDSM_X4(a[p][mf], addr);
            }
#pragma unroll
        for (int np = 0; np < 2; np++) {
            uint32_t addr = bs_base + 2u * (uint32_t)(
                (buf * BK + lrow) * BW + wn0 + np * 16 + lcol);
            LDSM_X4_T(b[np], addr);
        }

#pragma unroll
        for (int mf = 0; mf < 2; mf++)
#pragma unroll
            for (int nf = 0; nf < 4; nf++) {
                const uint32_t b0 = b[nf >> 1][(nf & 1) * 2];
                const uint32_t b1 = b[nf >> 1][(nf & 1) * 2 + 1];
                MMA_BF16(c[mf][nf], a[0][mf], b0, b1);
                MMA_BF16(c[mf][nf], a[1][mf], b0, b1);
                MMA_BF16(c[mf][nf], a[2][mf], b0, b1);
            }

        if (kt + 1 < NT) sstore(buf ^ 1);
        __syncthreads();
        buf ^= 1;
    }

    // epilogue: c frag (mf,nf): rows g, g+8 ; cols t4*2, +1
    const int g  = lane >> 2;
    const int t4 = lane & 3;
    float* outI = g_I + (size_t)kz * B_DIM * N_DIM;
#pragma unroll
    for (int mf = 0; mf < 2; mf++)
#pragma unroll
        for (int nf = 0; nf < 4; nf++) {
            const int r  = row0 + wm0 + mf * 16 + g;
            const int cc = col0 + wn0 + nf * 8 + t4 * 2;
            float2 lo; lo.x = c[mf][nf][0]; lo.y = c[mf][nf][1];
            float2 hi; hi.x = c[mf][nf][2]; hi.y = c[mf][nf][3];
            *reinterpret_cast<float2*>(outI + (size_t)r * N_DIM + cc)       = lo;
            *reinterpret_cast<float2*>(outI + (size_t)(r + 8) * N_DIM + cc) = hi;
        }
}

// ---------------------------------------------------------------------------
// Kernel 2: LIF recurrence (unchanged — at its DRAM-write ceiling).
//   u = rn(rn(ALPHA*V) + I)  (explicit mul/add, no FMA contraction)
//   V' = Z ? 0 : u ;  Z' = (V' >= 1)
// ---------------------------------------------------------------------------
__global__ void __launch_bounds__(256) spike_kernel(float* __restrict__ out)
{
    const int g  = blockIdx.x * blockDim.x + threadIdx.x;   // 0 .. B*N/4
    const int n4 = g % (N_DIM / 4);
    const int b  = g / (N_DIM / 4);

    const size_t off = (size_t)b * N_DIM + n4 * 4;
    const size_t stride = (size_t)B_DIM * N_DIM;
    const float4 p0 = *reinterpret_cast<const float4*>(g_I + off);
    const float4 p1 = *reinterpret_cast<const float4*>(g_I + off + stride);
    const float4 p2 = *reinterpret_cast<const float4*>(g_I + off + 2 * stride);
    const float4 p3 = *reinterpret_cast<const float4*>(g_I + off + 3 * stride);
    const float4 I4 = make_float4(
        __fadd_rn(__fadd_rn(p0.x, p1.x), __fadd_rn(p2.x, p3.x)),
        __fadd_rn(__fadd_rn(p0.y, p1.y), __fadd_rn(p2.y, p3.y)),
        __fadd_rn(__fadd_rn(p0.z, p1.z), __fadd_rn(p2.z, p3.z)),
        __fadd_rn(__fadd_rn(p0.w, p1.w), __fadd_rn(p2.w, p3.w)));

    float v0 = 0.f, v1 = 0.f, v2 = 0.f, v3 = 0.f;
    bool  s0 = false, s1 = false, s2 = false, s3 = false;

    float* outp = out + (size_t)b * T_DIM * N_DIM + n4 * 4;

#pragma unroll 8
    for (int t = 0; t < T_DIM; t++) {
        float u0 = __fadd_rn(__fmul_rn(ALPHA_F, v0), I4.x);
        float u1 = __fadd_rn(__fmul_rn(ALPHA_F, v1), I4.y);
        float u2 = __fadd_rn(__fmul_rn(ALPHA_F, v2), I4.z);
        float u3 = __fadd_rn(__fmul_rn(ALPHA_F, v3), I4.w);
        v0 = s0 ? 0.0f : u0;
        v1 = s1 ? 0.0f : u1;
        v2 = s2 ? 0.0f : u2;
        v3 = s3 ? 0.0f : u3;
        s0 = (v0 >= THRESH_F);
        s1 = (v1 >= THRESH_F);
        s2 = (v2 >= THRESH_F);
        s3 = (v3 >= THRESH_F);
        float4 z = make_float4(s0 ? 1.0f : 0.0f, s1 ? 1.0f : 0.0f,
                               s2 ? 1.0f : 0.0f, s3 ? 1.0f : 0.0f);
        __stcs(reinterpret_cast<float4*>(outp), z);
        outp += N_DIM;
    }
}

// ---------------------------------------------------------------------------
extern "C" void kernel_launch(void* const* d_in, const int* in_sizes, int n_in,
                              void* d_out, int out_size)
{
    const float* x = (const float*)d_in[0];   // [256, 2048]
    const float* W = (const float*)d_in[1];   // [2048, 2048]
    float* out = (float*)d_out;               // [256, 128, 2048]

    split_kernel<<<(B_DIM * K_DIM / 4) / 256, 256>>>(x);

    dim3 gemm_grid(N_DIM / BN, B_DIM / BM, SPLITK);   // (16, 4, 4) = 256 CTAs
    gemm_kernel<<<gemm_grid, 256>>>(W);

    const int spike_threads = (B_DIM * N_DIM) / 4;    // 131072
    spike_kernel<<<spike_threads / 256, 256>>>(out);
}